// round 5
// baseline (speedup 1.0000x reference)
#include <cuda_runtime.h>

// AttentionOptimizer: out = spins - LR*(grads + SMOOTH*g_smooth) + noise
// g_smooth = conv3(u)/conv3(v),  u = g*exp(-BETA*|g|), v = exp(-BETA*|g|),
// separable per-axis kernel w[d] = exp(-0.0125*(d*2/19)^2).
//
// R5: one kernel, CTA per (b, y_out), 800 threads. The y-reduction is split
// in half across thread pairs (h = 0/1); by linearity each half runs its own
// z-conv and x-conv on its partial plane, and the two partial results are
// combined only once at the very end. Halves the phase-1 serial LDG/MUFU/FMA
// chain and doubles warps/SM for latency hiding.

#define LLAT 20
#define PLANE 400                 // LLAT*LLAT
#define NPTS 8000                 // LLAT^3
#define NTHR 800

// Packed f32x2 FMA (sm_103a): d = a*b + c on both lanes.
static __device__ __forceinline__ float2 fma2(float2 a, float2 b, float2 c) {
    float2 d;
    asm("fma.rn.f32x2 %0, %1, %2, %3;"
        : "=l"(*reinterpret_cast<unsigned long long*>(&d))
        : "l"(*reinterpret_cast<unsigned long long*>(&a)),
          "l"(*reinterpret_cast<unsigned long long*>(&b)),
          "l"(*reinterpret_cast<unsigned long long*>(&c)));
    return d;
}

static __device__ __forceinline__ float2 add2(float2 a, float2 b) {
    return make_float2(a.x + b.x, a.y + b.y);
}

__global__ void __launch_bounds__(NTHR, 1)
attn_opt_fused(const float* __restrict__ grads,
               const float* __restrict__ spins,
               const float* __restrict__ noise,
               float* __restrict__ out)
{
    __shared__ float2 Vp[2][PLANE];           // per-half y-partial planes
    __shared__ float2 Tp[2][PLANE];           // per-half z-conv partials
    __shared__ float2 w2[2 * LLAT - 1];

    const int t  = threadIdx.x;
    const int h  = (t >= PLANE) ? 1 : 0;      // y-half
    const int tp = t - h * PLANE;             // tp = xp*20 + zp
    const int b  = blockIdx.x / LLAT;
    const int yo = blockIdx.x - b * LLAT;     // output y-plane
    const int xp = tp / LLAT;
    const int zp = tp - xp * LLAT;

    // Hoisted epilogue operands (h==0 only): DRAM latency hides under convs.
    const int gi = b * NPTS + xp * PLANE + yo * LLAT + zp;
    float s_v = 0.0f, n_v = 0.0f, g_v = 0.0f;
    if (h == 0) { s_v = spins[gi]; n_v = noise[gi]; g_v = grads[gi]; }

    // Weight table: w[d] = exp(-0.0125*(d*2/19)^2), d in [-19,19], dup-packed.
    if (t < 2 * LLAT - 1) {
        const float d = (float)(t - (LLAT - 1)) * (2.0f / (float)(LLAT - 1));
        const float w = __expf(-0.0125f * d * d);
        w2[t] = make_float2(w, w);
    }

    // Phase 1 (split): partial y-reduction over 10 y' values per thread.
    const float* gcol = grads + b * NPTS + xp * PLANE + zp;
    float gc[LLAT / 2];
#pragma unroll
    for (int k = 0; k < LLAT / 2; k++)
        gc[k] = gcol[(h * (LLAT / 2) + k) * LLAT];

    __syncthreads();   // w2 ready

    float2 acc = make_float2(0.0f, 0.0f);
#pragma unroll
    for (int k = 0; k < LLAT / 2; k++) {
        const int yp = h * (LLAT / 2) + k;
        const float e = __expf(-2.0f * fabsf(gc[k]));
        const float2 ue = make_float2(gc[k] * e, e);
        acc = fma2(ue, w2[(LLAT - 1) + yo - yp], acc);   // broadcast LDS.64
    }
    Vp[h][tp] = acc;
    __syncthreads();

    // Phase 2 (per half): z-conv. Tp[h][xp][zp] = sum_j w[zp-j] Vp[h][xp][j]
    acc = make_float2(0.0f, 0.0f);
#pragma unroll
    for (int j = 0; j < LLAT; j++)
        acc = fma2(Vp[h][xp * LLAT + j], w2[(LLAT - 1) + zp - j], acc);
    Tp[h][tp] = acc;
    __syncthreads();

    // Phase 3 (per half): x-conv. Rp = sum_j w[xp-j] Tp[h][j][zp]
    acc = make_float2(0.0f, 0.0f);
#pragma unroll
    for (int j = 0; j < LLAT; j++)
        acc = fma2(Tp[h][j * LLAT + zp], w2[(LLAT - 1) + xp - j], acc);

    // Combine halves (reuse Vp[1] as staging) + epilogue by h==0 threads.
    if (h == 1) Vp[1][tp] = acc;
    __syncthreads();

    if (h == 0) {
        const float2 r = add2(acc, Vp[1][tp]);
        out[gi] = s_v - 0.05f * g_v - 0.5f * __fdividef(r.x, r.y) + n_v;
    }
}

extern "C" void kernel_launch(void* const* d_in, const int* in_sizes, int n_in,
                              void* d_out, int out_size)
{
    const float* grads = (const float*)d_in[0];
    const float* spins = (const float*)d_in[1];
    // d_in[2] = pos: unused — lattice geometry is known analytically.
    const float* noise = (const float*)d_in[3];
    float* out = (float*)d_out;

    const int B = in_sizes[0] / NPTS;
    attn_opt_fused<<<B * LLAT, NTHR>>>(grads, spins, noise, out);
}